// round 3
// baseline (speedup 1.0000x reference)
#include <cuda_runtime.h>
#include <cstdint>
#include <cfloat>
#include <math.h>

#define KNN1    11            // top-11 including self (rank 0 = self, d2 = 0)
#define TPB     256
#define WARPS   8
#define PPB     32            // points per block (lane <-> point)
#define TILE    512
#define BUFSZ   24
#define MAXN    16896
#define MAXB    8
#define MAXPAIRS (MAXB*(MAXB-1)/2)
#define D2MASK  0xFFFFC000u
#define IDXMASK 0x3FFFu

__device__ float4 g_pos4[MAXN];
__device__ float4 g_norm4[MAXN];
__device__ float  g_acc[3];   // [0]=depth sum, [1]=normal sum, [2]=epipolar sum
                              // zero at process start; finalize re-zeros each replay

// ---------------------------------------------------------------------------
// Prep: per-block fundamental matrices (in smem), quaternion->normal, camera
// projections, depth & epipolar contributions, packed positions for KNN.
// ---------------------------------------------------------------------------
__global__ void prep_kernel(const float* __restrict__ pos,
                            const float* __restrict__ rot,
                            const float* __restrict__ opac,
                            const float* __restrict__ view,
                            int N, int B, int Npad) {
    __shared__ float sF[MAXPAIRS * 9];
    __shared__ float s_d, s_e;
    int n = blockIdx.x * blockDim.x + threadIdx.x;

    if (threadIdx.x == 0) {
        s_d = 0.f; s_e = 0.f;
        // camera centers
        float C[MAXB][3];
        for (int b = 0; b < B; b++) {
            const float* V = view + b * 16;
            float m00 = V[0], m01 = V[1], m02 = V[2];
            float m10 = V[4], m11 = V[5], m12 = V[6];
            float m20 = V[8], m21 = V[9], m22 = V[10];
            float t0 = V[3], t1 = V[7], t2 = V[11];
            float c00 = m11 * m22 - m12 * m21;
            float c01 = m12 * m20 - m10 * m22;
            float c02 = m10 * m21 - m11 * m20;
            float id = 1.0f / (m00 * c00 + m01 * c01 + m02 * c02);
            float i00 = c00 * id, i01 = (m02 * m21 - m01 * m22) * id, i02 = (m01 * m12 - m02 * m11) * id;
            float i10 = c01 * id, i11 = (m00 * m22 - m02 * m20) * id, i12 = (m02 * m10 - m00 * m12) * id;
            float i20 = c02 * id, i21 = (m01 * m20 - m00 * m21) * id, i22 = (m00 * m11 - m01 * m10) * id;
            C[b][0] = -(i00 * t0 + i01 * t1 + i02 * t2);
            C[b][1] = -(i10 * t0 + i11 * t1 + i12 * t2);
            C[b][2] = -(i20 * t0 + i21 * t1 + i22 * t2);
        }
        int pr = 0;
        for (int i = 0; i < B; i++) {
            for (int j = i + 1; j < B; j++) {
                const float* Vi = view + i * 16;
                const float* Vj = view + j * 16;
                float tx = C[j][0] - C[i][0];
                float ty = C[j][1] - C[i][1];
                float tz = C[j][2] - C[i][2];
                float R[3][3];
                for (int r = 0; r < 3; r++)
                    for (int c = 0; c < 3; c++)
                        R[r][c] = Vj[r * 4 + 0] * Vi[c * 4 + 0]
                                + Vj[r * 4 + 1] * Vi[c * 4 + 1]
                                + Vj[r * 4 + 2] * Vi[c * 4 + 2];
                float* F = &sF[pr * 9];
                for (int c = 0; c < 3; c++) {
                    F[0 * 3 + c] = -tz * R[1][c] + ty * R[2][c];
                    F[1 * 3 + c] =  tz * R[0][c] - tx * R[2][c];
                    F[2 * 3 + c] = -ty * R[0][c] + tx * R[1][c];
                }
                pr++;
            }
        }
    }
    __syncthreads();

    float dct = 0.f, ect = 0.f;
    if (n < N) {
        float qw = rot[n * 4 + 0], qx = rot[n * 4 + 1];
        float qy = rot[n * 4 + 2], qz = rot[n * 4 + 3];
        float qn = 1.0f / sqrtf(qw * qw + qx * qx + qy * qy + qz * qz);
        qw *= qn; qx *= qn; qy *= qn; qz *= qn;
        float nx = 2.f * qx * qz + 2.f * qw * qy;
        float ny = 2.f * qy * qz - 2.f * qw * qx;
        float nz = 1.f - 2.f * qx * qx - 2.f * qy * qy;
        g_norm4[n] = make_float4(nx, ny, nz, 0.f);

        float px = pos[n * 3 + 0], py = pos[n * 3 + 1], pz = pos[n * 3 + 2];
        g_pos4[n] = make_float4(px, py, pz, 0.f);

        float op = opac[n];
        float wd[MAXB], ptx[MAXB], pty[MAXB];
        for (int b = 0; b < B; b++) {
            const float* V = view + b * 16;
            float cx = V[0] * px + V[1] * py + V[2]  * pz + V[3];
            float cy = V[4] * px + V[5] * py + V[6]  * pz + V[7];
            float cz = V[8] * px + V[9] * py + V[10] * pz + V[11];
            wd[b] = cz * op;
            float den = fmaxf(cz, 1e-8f);
            ptx[b] = cx / den;
            pty[b] = cy / den;
        }
        for (int b = 0; b + 1 < B; b++) dct += fabsf(wd[b] - wd[b + 1]);

        int pr = 0;
        for (int i = 0; i < B; i++) {
            for (int j = i + 1; j < B; j++) {
                const float* F = &sF[pr * 9];
                float l0 = F[0] * ptx[i] + F[1] * pty[i] + F[2];
                float l1 = F[3] * ptx[i] + F[4] * pty[i] + F[5];
                float l2 = F[6] * ptx[i] + F[7] * pty[i] + F[8];
                float e = fabsf(ptx[j] * l0 + pty[j] * l1 + l2);
                ect += e / (sqrtf(l0 * l0 + l1 * l1) + 1e-8f);
                pr++;
            }
        }
        ect *= op;
    } else if (n < Npad) {
        g_pos4[n] = make_float4(1e18f, 1e18f, 1e18f, 0.f);  // sentinel pad
    }

    atomicAdd(&s_d, dct);
    atomicAdd(&s_e, ect);
    __syncthreads();
    if (threadIdx.x == 0) {
        atomicAdd(&g_acc[0], s_d);
        atomicAdd(&g_acc[2], s_e);
    }
}

// ---------------------------------------------------------------------------
// KNN + normal loss. Lane <-> point (broadcast tile reads), warp <-> candidate
// segment. Branch-free predicated hot loop buffering packed (d2|idx) keys;
// rare ballot-triggered flushes into a register-resident sorted top-11.
// ---------------------------------------------------------------------------
__global__ void __launch_bounds__(TPB)
knn_kernel(const float* __restrict__ opac, int N, int nTiles) {
    __shared__ float4   s_tile[TILE];
    __shared__ uint32_t s_buf[BUFSZ * TPB];   // [slot][warp*32+lane] -> bank = lane
    __shared__ float    s_nl;

    int tid = threadIdx.x;
    int w   = tid >> 5;         // warp = candidate segment
    int l   = tid & 31;         // lane = point
    int p   = blockIdx.x * PPB + l;
    if (tid == 0) s_nl = 0.f;

    int pc = (p < N) ? p : 0;
    float4 me = g_pos4[pc];

    uint32_t hk[KNN1];
#pragma unroll
    for (int q = 0; q < KNN1; q++) hk[q] = 0xFFFFFFFFu;
    uint32_t tau = 0xFFFFFFFFu;
    int cnt = 0;
    const int jb = w * (TILE / WARPS);   // 64 candidates per warp per tile

    for (int t = 0; t < nTiles; t++) {
        __syncthreads();
        int tbase = t * TILE;
        s_tile[tid]       = g_pos4[tbase + tid];
        s_tile[tid + TPB] = g_pos4[tbase + tid + TPB];
        __syncthreads();

#pragma unroll 1
        for (int g = 0; g < TILE / WARPS; g += 8) {
#pragma unroll
            for (int k = 0; k < 8; k++) {
                int jj = jb + g + k;                     // uniform across warp
                float4 c = s_tile[jj];                   // broadcast LDS.128
                float dx = me.x - c.x;
                float dy = me.y - c.y;
                float dz = me.z - c.z;
                float d2 = fmaf(dx, dx, fmaf(dy, dy, dz * dz));
                uint32_t key = (__float_as_uint(d2) & D2MASK) | (uint32_t)(tbase + jj);
                if (key < tau) {                         // predicated STS + IADD
                    s_buf[cnt * TPB + tid] = key;
                    cnt++;
                }
            }
            if (__ballot_sync(0xFFFFFFFFu, cnt > BUFSZ - 8)) {
                for (int i = 0; i < cnt; i++) {
                    uint32_t v = s_buf[i * TPB + tid];
                    if (v < tau) {
#pragma unroll
                        for (int q = 0; q < KNN1; q++) {
                            uint32_t h = hk[q];
                            bool sw = v < h;
                            hk[q] = sw ? v : h;
                            v     = sw ? h : v;
                        }
                        tau = hk[KNN1 - 1];
                    }
                }
                cnt = 0;
            }
        }
    }
    // final flush
    for (int i = 0; i < cnt; i++) {
        uint32_t v = s_buf[i * TPB + tid];
        if (v < tau) {
#pragma unroll
            for (int q = 0; q < KNN1; q++) {
                uint32_t h = hk[q];
                bool sw = v < h;
                hk[q] = sw ? v : h;
                v     = sw ? h : v;
            }
            tau = hk[KNN1 - 1];
        }
    }

    __syncthreads();
    // publish sorted lists (reuse buffer region): [rank][warp*32+lane]
#pragma unroll
    for (int q = 0; q < KNN1; q++) s_buf[q * TPB + tid] = hk[q];
    __syncthreads();

    // 8-way merge: one thread per point (threads 0..31)
    if (tid < PPB) {
        int pp = blockIdx.x * PPB + tid;
        if (pp < N) {
            int head[WARPS];
#pragma unroll
            for (int u = 0; u < WARPS; u++) head[u] = 0;
            float4 nm = g_norm4[pp];
            float acc = 0.f;
            for (int r = 0; r < KNN1; r++) {
                uint32_t best = 0xFFFFFFFFu; int bw = 0;
#pragma unroll
                for (int u = 0; u < WARPS; u++) {
                    uint32_t v = (head[u] < KNN1)
                               ? s_buf[head[u] * TPB + u * 32 + tid]
                               : 0xFFFFFFFFu;
                    if (v < best) { best = v; bw = u; }
                }
#pragma unroll
                for (int u = 0; u < WARPS; u++) if (u == bw) head[u]++;
                if (r > 0) {   // rank 0 = self (d2 = 0)
                    int nb = (int)(best & IDXMASK);
                    float4 nn = g_norm4[nb];
                    acc += 1.0f - (nm.x * nn.x + nm.y * nn.y + nm.z * nn.z);
                }
            }
            atomicAdd(&s_nl, opac[pp] * (acc * (1.0f / (float)(KNN1 - 1))));
        }
    }
    __syncthreads();
    if (tid == 0) atomicAdd(&g_acc[1], s_nl);
}

// ---------------------------------------------------------------------------
// Finalize: combine losses, then reset accumulators for the next replay.
// ---------------------------------------------------------------------------
__global__ void finalize_kernel(float* out, int N, int B) {
    int bm1 = (B - 1) < 1 ? 1 : (B - 1);
    int pairs = B * (B - 1) / 2; if (pairs < 1) pairs = 1;
    float depth  = g_acc[0] / ((float)N * (float)bm1);
    float normal = g_acc[1] / (float)N;
    float ep     = g_acc[2] / (float)pairs;
    out[0] = depth + normal + ep;
    g_acc[0] = 0.f; g_acc[1] = 0.f; g_acc[2] = 0.f;
}

// ---------------------------------------------------------------------------
extern "C" void kernel_launch(void* const* d_in, const int* in_sizes, int n_in,
                              void* d_out, int out_size) {
    const float* pos  = (const float*)d_in[0];
    const float* rot  = (const float*)d_in[1];
    const float* opac = (const float*)d_in[2];
    const float* view = (const float*)d_in[3];

    int N = in_sizes[0] / 3;
    int B = in_sizes[3] / 16;
    int nTiles = (N + TILE - 1) / TILE;
    int Npad = nTiles * TILE;

    prep_kernel<<<(Npad + TPB - 1) / TPB, TPB>>>(pos, rot, opac, view, N, B, Npad);
    knn_kernel<<<(N + PPB - 1) / PPB, TPB>>>(opac, N, nTiles);
    finalize_kernel<<<1, 1>>>((float*)d_out, N, B);
}

// round 4
// speedup vs baseline: 1.1649x; 1.1649x over previous
#include <cuda_runtime.h>
#include <cstdint>
#include <cfloat>
#include <math.h>

#define KNN1    11            // top-11 including self (rank 0 = self, d2 = 0)
#define TPB     256
#define WARPS   8
#define PPB     32            // points per block (lane <-> point)
#define TILE    512
#define SEG     (TILE / WARPS)
#define BUFSZ   24
#define PREPTPB 128
#define MAXN    16384         // idx must fit 14 bits
#define MAXB    8
#define MAXPAIRS (MAXB*(MAXB-1)/2)
#define D2MASK  0xFFFFC000u
#define IDXMASK 0x3FFFu

__device__ float4   g_pos4[MAXN];     // xyz + 0.5*|c|^2
__device__ float4   g_norm4[MAXN];
__device__ float    g_acc[3];         // [0]=depth, [1]=normal, [2]=epipolar (sums)
__device__ unsigned g_done = 0;       // last-block ticket; reset by finalize path

// ---------------------------------------------------------------------------
__device__ __forceinline__ void camera_center(const float* V, float* C) {
    float m00 = V[0], m01 = V[1], m02 = V[2];
    float m10 = V[4], m11 = V[5], m12 = V[6];
    float m20 = V[8], m21 = V[9], m22 = V[10];
    float t0 = V[3], t1 = V[7], t2 = V[11];
    float c00 = m11 * m22 - m12 * m21;
    float c01 = m12 * m20 - m10 * m22;
    float c02 = m10 * m21 - m11 * m20;
    float id = 1.0f / (m00 * c00 + m01 * c01 + m02 * c02);
    float i00 = c00 * id, i01 = (m02 * m21 - m01 * m22) * id, i02 = (m01 * m12 - m02 * m11) * id;
    float i10 = c01 * id, i11 = (m00 * m22 - m02 * m20) * id, i12 = (m02 * m10 - m00 * m12) * id;
    float i20 = c02 * id, i21 = (m01 * m20 - m00 * m21) * id, i22 = (m00 * m11 - m01 * m10) * id;
    C[0] = -(i00 * t0 + i01 * t1 + i02 * t2);
    C[1] = -(i10 * t0 + i11 * t1 + i12 * t2);
    C[2] = -(i20 * t0 + i21 * t1 + i22 * t2);
}

// ---------------------------------------------------------------------------
// Prep: F matrices computed IN PARALLEL (one thread per view pair), then
// per-point normal / projection / depth / epipolar contributions.
// ---------------------------------------------------------------------------
__global__ void __launch_bounds__(PREPTPB)
prep_kernel(const float* __restrict__ pos,
            const float* __restrict__ rot,
            const float* __restrict__ opac,
            const float* __restrict__ view,
            int N, int B, int Npad) {
    __shared__ float sF[MAXPAIRS * 9];
    __shared__ float s_d, s_e;
    int tx = threadIdx.x;
    int n = blockIdx.x * blockDim.x + tx;
    int pairs = B * (B - 1) / 2;

    if (tx == PREPTPB - 1) { s_d = 0.f; s_e = 0.f; }
    if (tx < pairs) {
        // decode linear pair index -> (i, j)
        int pr = tx, i = 0;
        while (pr >= B - 1 - i) { pr -= B - 1 - i; i++; }
        int j = i + 1 + pr;
        const float* Vi = view + i * 16;
        const float* Vj = view + j * 16;
        float Ci[3], Cj[3];
        camera_center(Vi, Ci);
        camera_center(Vj, Cj);
        float txv = Cj[0] - Ci[0];
        float tyv = Cj[1] - Ci[1];
        float tzv = Cj[2] - Ci[2];
        float R[3][3];
        for (int r = 0; r < 3; r++)
            for (int c = 0; c < 3; c++)
                R[r][c] = Vj[r * 4 + 0] * Vi[c * 4 + 0]
                        + Vj[r * 4 + 1] * Vi[c * 4 + 1]
                        + Vj[r * 4 + 2] * Vi[c * 4 + 2];
        float* F = &sF[tx * 9];
        for (int c = 0; c < 3; c++) {
            F[0 * 3 + c] = -tzv * R[1][c] + tyv * R[2][c];
            F[1 * 3 + c] =  tzv * R[0][c] - txv * R[2][c];
            F[2 * 3 + c] = -tyv * R[0][c] + txv * R[1][c];
        }
    }
    __syncthreads();

    float dct = 0.f, ect = 0.f;
    if (n < N) {
        float qw = rot[n * 4 + 0], qx = rot[n * 4 + 1];
        float qy = rot[n * 4 + 2], qz = rot[n * 4 + 3];
        float qn = 1.0f / sqrtf(qw * qw + qx * qx + qy * qy + qz * qz);
        qw *= qn; qx *= qn; qy *= qn; qz *= qn;
        float nx = 2.f * qx * qz + 2.f * qw * qy;
        float ny = 2.f * qy * qz - 2.f * qw * qx;
        float nz = 1.f - 2.f * qx * qx - 2.f * qy * qy;
        g_norm4[n] = make_float4(nx, ny, nz, 0.f);

        float px = pos[n * 3 + 0], py = pos[n * 3 + 1], pz = pos[n * 3 + 2];
        float sq = px * px + py * py + pz * pz;
        g_pos4[n] = make_float4(px, py, pz, 0.5f * sq);

        float op = opac[n];
        float wd[MAXB], ptx[MAXB], pty[MAXB];
        for (int b = 0; b < B; b++) {
            const float* V = view + b * 16;
            float cx = V[0] * px + V[1] * py + V[2]  * pz + V[3];
            float cy = V[4] * px + V[5] * py + V[6]  * pz + V[7];
            float cz = V[8] * px + V[9] * py + V[10] * pz + V[11];
            wd[b] = cz * op;
            float inv = 1.0f / fmaxf(cz, 1e-8f);
            ptx[b] = cx * inv;
            pty[b] = cy * inv;
        }
        for (int b = 0; b + 1 < B; b++) dct += fabsf(wd[b] - wd[b + 1]);

        int pr = 0;
        for (int i = 0; i < B; i++) {
            for (int j = i + 1; j < B; j++) {
                const float* F = &sF[pr * 9];
                float l0 = F[0] * ptx[i] + F[1] * pty[i] + F[2];
                float l1 = F[3] * ptx[i] + F[4] * pty[i] + F[5];
                float l2 = F[6] * ptx[i] + F[7] * pty[i] + F[8];
                float e = fabsf(ptx[j] * l0 + pty[j] * l1 + l2);
                ect += e / (sqrtf(l0 * l0 + l1 * l1) + 1e-8f);
                pr++;
            }
        }
        ect *= op;
    } else if (n < Npad) {
        g_pos4[n] = make_float4(1e15f, 1e15f, 1e15f, 1e30f);  // sentinel pad
    }

    atomicAdd(&s_d, dct);
    atomicAdd(&s_e, ect);
    __syncthreads();
    if (tx == 0) {
        atomicAdd(&g_acc[0], s_d);
        atomicAdd(&g_acc[2], s_e);
    }
}

// ---------------------------------------------------------------------------
// KNN + normal loss + fused finalize.
// Hot loop ranks by m = 0.5|c|^2 - p.c  (monotone in d2): 3 FFMA + setp +
// predicated index-only buffer store. Exact d2 + packed key computed only at
// flush time (~60 items/lane total).
// ---------------------------------------------------------------------------
__global__ void __launch_bounds__(TPB)
knn_kernel(const float* __restrict__ opac, float* __restrict__ out,
           int N, int B, int nTiles) {
    __shared__ float4   s_tile[TILE];
    __shared__ uint32_t s_buf[BUFSZ * TPB];   // [slot][tid] -> bank = lane
    __shared__ float    s_nl;
    __shared__ int      s_last;

    int tid = threadIdx.x;
    int w   = tid >> 5;         // warp = candidate segment
    int l   = tid & 31;         // lane = point
    int p   = blockIdx.x * PPB + l;
    if (tid == 0) { s_nl = 0.f; s_last = 0; }

    int pc = (p < N) ? p : 0;
    float4 me = g_pos4[pc];
    float nmx = -me.x, nmy = -me.y, nmz = -me.z;
    float sq_p = 2.0f * me.w;

    uint32_t hk[KNN1];
#pragma unroll
    for (int q = 0; q < KNN1; q++) hk[q] = 0xFFFFFFFFu;
    float tau_m = FLT_MAX;
    int cnt = 0;
    const int jb = w * SEG;

    for (int t = 0; t < nTiles; t++) {
        __syncthreads();
        int tbase = t * TILE;
        s_tile[tid]       = g_pos4[tbase + tid];
        s_tile[tid + TPB] = g_pos4[tbase + tid + TPB];
        __syncthreads();

#pragma unroll 1
        for (int g = 0; g < SEG; g += 8) {
#pragma unroll
            for (int k = 0; k < 8; k++) {
                int jj = jb + g + k;                 // uniform across warp
                float4 c = s_tile[jj];               // broadcast LDS.128
                float m = fmaf(nmx, c.x, c.w);
                m = fmaf(nmy, c.y, m);
                m = fmaf(nmz, c.z, m);
                if (m < tau_m) {                     // predicated STS + IADD
                    s_buf[cnt * TPB + tid] = (uint32_t)(tbase + jj);
                    cnt++;
                }
            }
            bool need = __ballot_sync(0xFFFFFFFFu, cnt > BUFSZ - 8) != 0;
            bool last_g = (g + 8 >= SEG);
            if (need || last_g) {                    // flush (warp-uniform)
                for (int i = 0; i < cnt; i++) {
                    uint32_t idx = s_buf[i * TPB + tid];
                    float4 c = s_tile[idx - (uint32_t)tbase];
                    float dx = me.x - c.x;
                    float dy = me.y - c.y;
                    float dz = me.z - c.z;
                    float d2 = fmaf(dx, dx, fmaf(dy, dy, dz * dz));
                    uint32_t v = (__float_as_uint(d2) & D2MASK) | idx;
                    if (v < hk[KNN1 - 1]) {
#pragma unroll
                        for (int q = 0; q < KNN1; q++) {
                            uint32_t h = hk[q];
                            bool sw = v < h;
                            hk[q] = sw ? v : h;
                            v     = sw ? h : v;
                        }
                    }
                }
                cnt = 0;
                uint32_t worst = hk[KNN1 - 1];
                if (worst != 0xFFFFFFFFu) {
                    // inflate quantized d2 by one quantum + eps: never reject
                    // a candidate that could beat/tie the current 11th.
                    float d2up = __uint_as_float((worst & D2MASK) + 0x4000u);
                    tau_m = 0.5f * (d2up - sq_p) + 1e-6f;
                }
            }
        }
    }

    __syncthreads();
    // publish sorted lists: [rank][tid]
#pragma unroll
    for (int q = 0; q < KNN1; q++) s_buf[q * TPB + tid] = hk[q];
    __syncthreads();

    // 8-way merge: one thread per point (threads 0..31)
    if (tid < PPB) {
        int pp = blockIdx.x * PPB + tid;
        if (pp < N) {
            int head[WARPS];
#pragma unroll
            for (int u = 0; u < WARPS; u++) head[u] = 0;
            float4 nm = g_norm4[pp];
            float acc = 0.f;
            for (int r = 0; r < KNN1; r++) {
                uint32_t best = 0xFFFFFFFFu; int bw = 0;
#pragma unroll
                for (int u = 0; u < WARPS; u++) {
                    uint32_t v = (head[u] < KNN1)
                               ? s_buf[head[u] * TPB + u * 32 + tid]
                               : 0xFFFFFFFFu;
                    if (v < best) { best = v; bw = u; }
                }
#pragma unroll
                for (int u = 0; u < WARPS; u++) if (u == bw) head[u]++;
                if (r > 0) {   // rank 0 = self (d2 = 0)
                    int nb = (int)(best & IDXMASK);
                    float4 nn = g_norm4[nb];
                    acc += 1.0f - (nm.x * nn.x + nm.y * nn.y + nm.z * nn.z);
                }
            }
            atomicAdd(&s_nl, opac[pp] * (acc * (1.0f / (float)(KNN1 - 1))));
        }
    }
    __syncthreads();

    // block contribution + last-block fused finalize
    if (tid == 0) {
        atomicAdd(&g_acc[1], s_nl);
        __threadfence();
        unsigned ticket = atomicAdd(&g_done, 1u);
        if (ticket == gridDim.x - 1) s_last = 1;
    }
    __syncthreads();
    if (s_last && tid == 0) {
        int bm1 = (B - 1) < 1 ? 1 : (B - 1);
        int pairs = B * (B - 1) / 2; if (pairs < 1) pairs = 1;
        float depth  = g_acc[0] / ((float)N * (float)bm1);
        float normal = g_acc[1] / (float)N;
        float ep     = g_acc[2] / (float)pairs;
        out[0] = depth + normal + ep;
        g_acc[0] = 0.f; g_acc[1] = 0.f; g_acc[2] = 0.f;   // reset for replay
        g_done = 0u;
    }
}

// ---------------------------------------------------------------------------
extern "C" void kernel_launch(void* const* d_in, const int* in_sizes, int n_in,
                              void* d_out, int out_size) {
    const float* pos  = (const float*)d_in[0];
    const float* rot  = (const float*)d_in[1];
    const float* opac = (const float*)d_in[2];
    const float* view = (const float*)d_in[3];

    int N = in_sizes[0] / 3;
    int B = in_sizes[3] / 16;
    int nTiles = (N + TILE - 1) / TILE;
    int Npad = nTiles * TILE;

    prep_kernel<<<(Npad + PREPTPB - 1) / PREPTPB, PREPTPB>>>(pos, rot, opac, view, N, B, Npad);
    knn_kernel<<<(N + PPB - 1) / PPB, TPB>>>(opac, (float*)d_out, N, B, nTiles);
}

// round 5
// speedup vs baseline: 1.1669x; 1.0017x over previous
#include <cuda_runtime.h>
#include <cstdint>
#include <cfloat>
#include <math.h>

#define KNN1    11            // top-11 including self (rank 0 = self, d2 = 0)
#define TPB     256
#define WARPS   8
#define PPB     32            // points per block (lane <-> point)
#define TILE    512
#define SEG     (TILE / WARPS)
#define BUFSZ   24
#define PREPTPB 128
#define MAXN    16384         // idx must fit 14 bits
#define MAXB    8
#define MAXPAIRS (MAXB*(MAXB-1)/2)
#define D2MASK  0xFFFFC000u
#define IDXMASK 0x3FFFu

__device__ float4   g_pos4[MAXN];     // xyz + 0.5*|c|^2
__device__ float4   g_norm4[MAXN];
__device__ float    g_acc[3];         // [0]=depth, [1]=normal, [2]=epipolar (sums)
__device__ unsigned g_done = 0;       // last-block ticket; reset by finalize path

// ---------------------------------------------------------------------------
__device__ __forceinline__ void camera_center(const float* V, float* C) {
    float m00 = V[0], m01 = V[1], m02 = V[2];
    float m10 = V[4], m11 = V[5], m12 = V[6];
    float m20 = V[8], m21 = V[9], m22 = V[10];
    float t0 = V[3], t1 = V[7], t2 = V[11];
    float c00 = m11 * m22 - m12 * m21;
    float c01 = m12 * m20 - m10 * m22;
    float c02 = m10 * m21 - m11 * m20;
    float id = 1.0f / (m00 * c00 + m01 * c01 + m02 * c02);
    float i00 = c00 * id, i01 = (m02 * m21 - m01 * m22) * id, i02 = (m01 * m12 - m02 * m11) * id;
    float i10 = c01 * id, i11 = (m00 * m22 - m02 * m20) * id, i12 = (m02 * m10 - m00 * m12) * id;
    float i20 = c02 * id, i21 = (m01 * m20 - m00 * m21) * id, i22 = (m00 * m11 - m01 * m10) * id;
    C[0] = -(i00 * t0 + i01 * t1 + i02 * t2);
    C[1] = -(i10 * t0 + i11 * t1 + i12 * t2);
    C[2] = -(i20 * t0 + i21 * t1 + i22 * t2);
}

// ---------------------------------------------------------------------------
// Prep: F matrices computed IN PARALLEL (one thread per view pair), then
// per-point normal / projection / depth / epipolar contributions.
// ---------------------------------------------------------------------------
__global__ void __launch_bounds__(PREPTPB)
prep_kernel(const float* __restrict__ pos,
            const float* __restrict__ rot,
            const float* __restrict__ opac,
            const float* __restrict__ view,
            int N, int B, int Npad) {
    __shared__ float sF[MAXPAIRS * 9];
    __shared__ float s_d, s_e;
    int tx = threadIdx.x;
    int n = blockIdx.x * blockDim.x + tx;
    int pairs = B * (B - 1) / 2;

    if (tx == PREPTPB - 1) { s_d = 0.f; s_e = 0.f; }
    if (tx < pairs) {
        // decode linear pair index -> (i, j)
        int pr = tx, i = 0;
        while (pr >= B - 1 - i) { pr -= B - 1 - i; i++; }
        int j = i + 1 + pr;
        const float* Vi = view + i * 16;
        const float* Vj = view + j * 16;
        float Ci[3], Cj[3];
        camera_center(Vi, Ci);
        camera_center(Vj, Cj);
        float txv = Cj[0] - Ci[0];
        float tyv = Cj[1] - Ci[1];
        float tzv = Cj[2] - Ci[2];
        float R[3][3];
        for (int r = 0; r < 3; r++)
            for (int c = 0; c < 3; c++)
                R[r][c] = Vj[r * 4 + 0] * Vi[c * 4 + 0]
                        + Vj[r * 4 + 1] * Vi[c * 4 + 1]
                        + Vj[r * 4 + 2] * Vi[c * 4 + 2];
        float* F = &sF[tx * 9];
        for (int c = 0; c < 3; c++) {
            F[0 * 3 + c] = -tzv * R[1][c] + tyv * R[2][c];
            F[1 * 3 + c] =  tzv * R[0][c] - txv * R[2][c];
            F[2 * 3 + c] = -tyv * R[0][c] + txv * R[1][c];
        }
    }
    __syncthreads();

    float dct = 0.f, ect = 0.f;
    if (n < N) {
        float qw = rot[n * 4 + 0], qx = rot[n * 4 + 1];
        float qy = rot[n * 4 + 2], qz = rot[n * 4 + 3];
        float qn = 1.0f / sqrtf(qw * qw + qx * qx + qy * qy + qz * qz);
        qw *= qn; qx *= qn; qy *= qn; qz *= qn;
        float nx = 2.f * qx * qz + 2.f * qw * qy;
        float ny = 2.f * qy * qz - 2.f * qw * qx;
        float nz = 1.f - 2.f * qx * qx - 2.f * qy * qy;
        g_norm4[n] = make_float4(nx, ny, nz, 0.f);

        float px = pos[n * 3 + 0], py = pos[n * 3 + 1], pz = pos[n * 3 + 2];
        float sq = px * px + py * py + pz * pz;
        g_pos4[n] = make_float4(px, py, pz, 0.5f * sq);

        float op = opac[n];
        float wd[MAXB], ptx[MAXB], pty[MAXB];
        for (int b = 0; b < B; b++) {
            const float* V = view + b * 16;
            float cx = V[0] * px + V[1] * py + V[2]  * pz + V[3];
            float cy = V[4] * px + V[5] * py + V[6]  * pz + V[7];
            float cz = V[8] * px + V[9] * py + V[10] * pz + V[11];
            wd[b] = cz * op;
            float inv = 1.0f / fmaxf(cz, 1e-8f);
            ptx[b] = cx * inv;
            pty[b] = cy * inv;
        }
        for (int b = 0; b + 1 < B; b++) dct += fabsf(wd[b] - wd[b + 1]);

        int pr = 0;
        for (int i = 0; i < B; i++) {
            for (int j = i + 1; j < B; j++) {
                const float* F = &sF[pr * 9];
                float l0 = F[0] * ptx[i] + F[1] * pty[i] + F[2];
                float l1 = F[3] * ptx[i] + F[4] * pty[i] + F[5];
                float l2 = F[6] * ptx[i] + F[7] * pty[i] + F[8];
                float e = fabsf(ptx[j] * l0 + pty[j] * l1 + l2);
                ect += e / (sqrtf(l0 * l0 + l1 * l1) + 1e-8f);
                pr++;
            }
        }
        ect *= op;
    } else if (n < Npad) {
        g_pos4[n] = make_float4(1e15f, 1e15f, 1e15f, 1e30f);  // sentinel pad
    }

    atomicAdd(&s_d, dct);
    atomicAdd(&s_e, ect);
    __syncthreads();
    if (tx == 0) {
        atomicAdd(&g_acc[0], s_d);
        atomicAdd(&g_acc[2], s_e);
    }
}

// ---------------------------------------------------------------------------
// KNN + normal loss + fused finalize.
// Hot loop ranks by m = 0.5|c|^2 - p.c  (monotone in d2): 3 FFMA + setp +
// predicated index-only buffer store. Exact d2 + packed key computed only at
// flush time (~60 items/lane total).
// ---------------------------------------------------------------------------
__global__ void __launch_bounds__(TPB)
knn_kernel(const float* __restrict__ opac, float* __restrict__ out,
           int N, int B, int nTiles) {
    __shared__ float4   s_tile[TILE];
    __shared__ uint32_t s_buf[BUFSZ * TPB];   // [slot][tid] -> bank = lane
    __shared__ float    s_nl;
    __shared__ int      s_last;

    int tid = threadIdx.x;
    int w   = tid >> 5;         // warp = candidate segment
    int l   = tid & 31;         // lane = point
    int p   = blockIdx.x * PPB + l;
    if (tid == 0) { s_nl = 0.f; s_last = 0; }

    int pc = (p < N) ? p : 0;
    float4 me = g_pos4[pc];
    float nmx = -me.x, nmy = -me.y, nmz = -me.z;
    float sq_p = 2.0f * me.w;

    uint32_t hk[KNN1];
#pragma unroll
    for (int q = 0; q < KNN1; q++) hk[q] = 0xFFFFFFFFu;
    float tau_m = FLT_MAX;
    int cnt = 0;
    const int jb = w * SEG;

    for (int t = 0; t < nTiles; t++) {
        __syncthreads();
        int tbase = t * TILE;
        s_tile[tid]       = g_pos4[tbase + tid];
        s_tile[tid + TPB] = g_pos4[tbase + tid + TPB];
        __syncthreads();

#pragma unroll 1
        for (int g = 0; g < SEG; g += 8) {
#pragma unroll
            for (int k = 0; k < 8; k++) {
                int jj = jb + g + k;                 // uniform across warp
                float4 c = s_tile[jj];               // broadcast LDS.128
                float m = fmaf(nmx, c.x, c.w);
                m = fmaf(nmy, c.y, m);
                m = fmaf(nmz, c.z, m);
                if (m < tau_m) {                     // predicated STS + IADD
                    s_buf[cnt * TPB + tid] = (uint32_t)(tbase + jj);
                    cnt++;
                }
            }
            bool need = __ballot_sync(0xFFFFFFFFu, cnt > BUFSZ - 8) != 0;
            bool last_g = (g + 8 >= SEG);
            if (need || last_g) {                    // flush (warp-uniform)
                for (int i = 0; i < cnt; i++) {
                    uint32_t idx = s_buf[i * TPB + tid];
                    float4 c = s_tile[idx - (uint32_t)tbase];
                    float dx = me.x - c.x;
                    float dy = me.y - c.y;
                    float dz = me.z - c.z;
                    float d2 = fmaf(dx, dx, fmaf(dy, dy, dz * dz));
                    uint32_t v = (__float_as_uint(d2) & D2MASK) | idx;
                    if (v < hk[KNN1 - 1]) {
#pragma unroll
                        for (int q = 0; q < KNN1; q++) {
                            uint32_t h = hk[q];
                            bool sw = v < h;
                            hk[q] = sw ? v : h;
                            v     = sw ? h : v;
                        }
                    }
                }
                cnt = 0;
                uint32_t worst = hk[KNN1 - 1];
                if (worst != 0xFFFFFFFFu) {
                    // inflate quantized d2 by one quantum + eps: never reject
                    // a candidate that could beat/tie the current 11th.
                    float d2up = __uint_as_float((worst & D2MASK) + 0x4000u);
                    tau_m = 0.5f * (d2up - sq_p) + 1e-6f;
                }
            }
        }
    }

    __syncthreads();
    // publish sorted lists: [rank][tid]
#pragma unroll
    for (int q = 0; q < KNN1; q++) s_buf[q * TPB + tid] = hk[q];
    __syncthreads();

    // 8-way merge: one thread per point (threads 0..31)
    if (tid < PPB) {
        int pp = blockIdx.x * PPB + tid;
        if (pp < N) {
            int head[WARPS];
#pragma unroll
            for (int u = 0; u < WARPS; u++) head[u] = 0;
            float4 nm = g_norm4[pp];
            float acc = 0.f;
            for (int r = 0; r < KNN1; r++) {
                uint32_t best = 0xFFFFFFFFu; int bw = 0;
#pragma unroll
                for (int u = 0; u < WARPS; u++) {
                    uint32_t v = (head[u] < KNN1)
                               ? s_buf[head[u] * TPB + u * 32 + tid]
                               : 0xFFFFFFFFu;
                    if (v < best) { best = v; bw = u; }
                }
#pragma unroll
                for (int u = 0; u < WARPS; u++) if (u == bw) head[u]++;
                if (r > 0) {   // rank 0 = self (d2 = 0)
                    int nb = (int)(best & IDXMASK);
                    float4 nn = g_norm4[nb];
                    acc += 1.0f - (nm.x * nn.x + nm.y * nn.y + nm.z * nn.z);
                }
            }
            atomicAdd(&s_nl, opac[pp] * (acc * (1.0f / (float)(KNN1 - 1))));
        }
    }
    __syncthreads();

    // block contribution + last-block fused finalize
    if (tid == 0) {
        atomicAdd(&g_acc[1], s_nl);
        __threadfence();
        unsigned ticket = atomicAdd(&g_done, 1u);
        if (ticket == gridDim.x - 1) s_last = 1;
    }
    __syncthreads();
    if (s_last && tid == 0) {
        int bm1 = (B - 1) < 1 ? 1 : (B - 1);
        int pairs = B * (B - 1) / 2; if (pairs < 1) pairs = 1;
        float depth  = g_acc[0] / ((float)N * (float)bm1);
        float normal = g_acc[1] / (float)N;
        float ep     = g_acc[2] / (float)pairs;
        out[0] = depth + normal + ep;
        g_acc[0] = 0.f; g_acc[1] = 0.f; g_acc[2] = 0.f;   // reset for replay
        g_done = 0u;
    }
}

// ---------------------------------------------------------------------------
extern "C" void kernel_launch(void* const* d_in, const int* in_sizes, int n_in,
                              void* d_out, int out_size) {
    const float* pos  = (const float*)d_in[0];
    const float* rot  = (const float*)d_in[1];
    const float* opac = (const float*)d_in[2];
    const float* view = (const float*)d_in[3];

    int N = in_sizes[0] / 3;
    int B = in_sizes[3] / 16;
    int nTiles = (N + TILE - 1) / TILE;
    int Npad = nTiles * TILE;

    prep_kernel<<<(Npad + PREPTPB - 1) / PREPTPB, PREPTPB>>>(pos, rot, opac, view, N, B, Npad);
    knn_kernel<<<(N + PPB - 1) / PPB, TPB>>>(opac, (float*)d_out, N, B, nTiles);
}